// round 1
// baseline (speedup 1.0000x reference)
#include <cuda_runtime.h>

typedef unsigned long long u64;

// ---------- packed f32x2 helpers (Blackwell FFMA2 path) ----------
__device__ __forceinline__ u64 pk2(float lo, float hi) {
    u64 r;
    asm("mov.b64 %0, {%1, %2};" : "=l"(r)
        : "r"(__float_as_uint(lo)), "r"(__float_as_uint(hi)));
    return r;
}
__device__ __forceinline__ void upk(u64 a, float& lo, float& hi) {
    unsigned int l_, h_;
    asm("mov.b64 {%0, %1}, %2;" : "=r"(l_), "=r"(h_) : "l"(a));
    lo = __uint_as_float(l_);
    hi = __uint_as_float(h_);
}
__device__ __forceinline__ u64 dfma(u64 a, u64 b, u64 c) {
    u64 d;
    asm("fma.rn.f32x2 %0, %1, %2, %3;" : "=l"(d) : "l"(a), "l"(b), "l"(c));
    return d;
}
__device__ __forceinline__ u64 dmul(u64 a, u64 b) {
    u64 d;
    asm("mul.rn.f32x2 %0, %1, %2;" : "=l"(d) : "l"(a), "l"(b));
    return d;
}
__device__ __forceinline__ u64 dadd(u64 a, u64 b) {
    u64 d;
    asm("add.rn.f32x2 %0, %1, %2;" : "=l"(d) : "l"(a), "l"(b));
    return d;
}
// 2*relu(x) per half, exact: x + |x|  (stays packed; the 2x is folded into
// pre-halved next-layer weights)
__device__ __forceinline__ u64 drelu2(u64 a) {
    return dadd(a, a & 0x7FFFFFFF7FFFFFFFULL);
}

// Process a packed pair of neighbors. ax/ay/az hold (coord of nbr A, coord of nbr B).
__device__ __forceinline__ void pair_step(
    u64 ax, u64 ay, u64 az,
    u64 npx, u64 npy, u64 npz,
    const u64* w1, const u64* bb1,
    const u64* w2, const u64* bb2,   // w2 pre-scaled by 0.5
    const u64* w3, u64 bb3,          // w3 pre-scaled by 0.5
    u64& vx, u64& vy, u64& vz)
{
    u64 dx = dadd(ax, npx);
    u64 dy = dadd(ay, npy);
    u64 dz = dadd(az, npz);
    u64 d2 = dfma(dx, dx, dfma(dy, dy, dmul(dz, dz)));
    float a, b;
    upk(d2, a, b);
    float ia = rsqrtf(fmaxf(a, 1e-24f));   // matches v/max(||v||,1e-12)
    float ib = rsqrtf(fmaxf(b, 1e-24f));
    u64 inv = pk2(ia, ib);
    u64 nx = dmul(dx, inv);
    u64 ny = dmul(dy, inv);
    u64 nz = dmul(dz, inv);

    // Layer 1: h_j = W1[j,:].nd + b1[j]
    u64 h0 = dfma(nz, w1[2],  dfma(ny, w1[1],  dfma(nx, w1[0],  bb1[0])));
    u64 h1 = dfma(nz, w1[5],  dfma(ny, w1[4],  dfma(nx, w1[3],  bb1[1])));
    u64 h2 = dfma(nz, w1[8],  dfma(ny, w1[7],  dfma(nx, w1[6],  bb1[2])));
    u64 h3 = dfma(nz, w1[11], dfma(ny, w1[10], dfma(nx, w1[9],  bb1[3])));
    u64 h4 = dfma(nz, w1[14], dfma(ny, w1[13], dfma(nx, w1[12], bb1[4])));
    h0 = drelu2(h0); h1 = drelu2(h1); h2 = drelu2(h2); h3 = drelu2(h3); h4 = drelu2(h4);

    // Layer 2: g_j = (W2/2)[j,:] . (2relu) + b2[j]
    u64 g0 = bb2[0], g1 = bb2[1], g2 = bb2[2], g3 = bb2[3], g4 = bb2[4];
    g0 = dfma(h0, w2[0],  g0); g0 = dfma(h1, w2[1],  g0); g0 = dfma(h2, w2[2],  g0);
    g0 = dfma(h3, w2[3],  g0); g0 = dfma(h4, w2[4],  g0);
    g1 = dfma(h0, w2[5],  g1); g1 = dfma(h1, w2[6],  g1); g1 = dfma(h2, w2[7],  g1);
    g1 = dfma(h3, w2[8],  g1); g1 = dfma(h4, w2[9],  g1);
    g2 = dfma(h0, w2[10], g2); g2 = dfma(h1, w2[11], g2); g2 = dfma(h2, w2[12], g2);
    g2 = dfma(h3, w2[13], g2); g2 = dfma(h4, w2[14], g2);
    g3 = dfma(h0, w2[15], g3); g3 = dfma(h1, w2[16], g3); g3 = dfma(h2, w2[17], g3);
    g3 = dfma(h3, w2[18], g3); g3 = dfma(h4, w2[19], g3);
    g4 = dfma(h0, w2[20], g4); g4 = dfma(h1, w2[21], g4); g4 = dfma(h2, w2[22], g4);
    g4 = dfma(h3, w2[23], g4); g4 = dfma(h4, w2[24], g4);
    g0 = drelu2(g0); g1 = drelu2(g1); g2 = drelu2(g2); g3 = drelu2(g3); g4 = drelu2(g4);

    // Layer 3: w = (W3/2).(2relu) + b3
    u64 w = bb3;
    w = dfma(g0, w3[0], w); w = dfma(g1, w3[1], w); w = dfma(g2, w3[2], w);
    w = dfma(g3, w3[3], w); w = dfma(g4, w3[4], w);

    // vel += nd * w
    vx = dfma(nx, w, vx);
    vy = dfma(ny, w, vy);
    vz = dfma(nz, w, vz);
}

__global__ void __launch_bounds__(128)
velvec_kernel(const float* __restrict__ pos, const float* __restrict__ nbr,
              const float* __restrict__ W1, const float* __restrict__ b1,
              const float* __restrict__ W2, const float* __restrict__ b2,
              const float* __restrict__ W3, const float* __restrict__ b3,
              float* __restrict__ out, int N)
{
    int n = blockIdx.x * blockDim.x + threadIdx.x;
    if (n >= N) return;

    // Broadcast-load MLP weights into packed (w,w) registers.
    u64 w1[15], bb1[5], w2[25], bb2[5], w3[5];
#pragma unroll
    for (int i = 0; i < 15; i++) { float v = __ldg(W1 + i);        w1[i]  = pk2(v, v); }
#pragma unroll
    for (int i = 0; i < 5;  i++) { float v = __ldg(b1 + i);        bb1[i] = pk2(v, v); }
#pragma unroll
    for (int i = 0; i < 25; i++) { float v = 0.5f * __ldg(W2 + i); w2[i]  = pk2(v, v); }
#pragma unroll
    for (int i = 0; i < 5;  i++) { float v = __ldg(b2 + i);        bb2[i] = pk2(v, v); }
#pragma unroll
    for (int i = 0; i < 5;  i++) { float v = 0.5f * __ldg(W3 + i); w3[i]  = pk2(v, v); }
    float b3v = __ldg(b3);
    u64 bb3 = pk2(b3v, b3v);

    float px = pos[3 * n + 0];
    float py = pos[3 * n + 1];
    float pz = pos[3 * n + 2];
    u64 npx = pk2(-px, -px), npy = pk2(-py, -py), npz = pk2(-pz, -pz);

    u64 vx = 0ULL, vy = 0ULL, vz = 0ULL;  // bit pattern 0 == (+0.f, +0.f)

    // Each point owns 32 neighbors * 3 floats = 96 floats = 24 float4 (384B aligned).
    const float4* base = reinterpret_cast<const float4*>(nbr) + (size_t)n * 24;

#pragma unroll 2
    for (int g = 0; g < 8; g++) {
        // Group of 4 neighbors = 12 floats = 3 x float4 (16B aligned: 48B stride)
        float4 q0 = base[3 * g + 0];  // x0 y0 z0 x1
        float4 q1 = base[3 * g + 1];  // y1 z1 x2 y2
        float4 q2 = base[3 * g + 2];  // z2 x3 y3 z3
        // pair (nbr 4g, 4g+1)
        pair_step(pk2(q0.x, q0.w), pk2(q0.y, q1.x), pk2(q0.z, q1.y),
                  npx, npy, npz, w1, bb1, w2, bb2, w3, bb3, vx, vy, vz);
        // pair (nbr 4g+2, 4g+3)
        pair_step(pk2(q1.z, q2.y), pk2(q1.w, q2.z), pk2(q2.x, q2.w),
                  npx, npy, npz, w1, bb1, w2, bb2, w3, bb3, vx, vy, vz);
    }

    float x0, x1, y0, y1, z0, z1;
    upk(vx, x0, x1); upk(vy, y0, y1); upk(vz, z0, z1);
    float fx = x0 + x1, fy = y0 + y1, fz = z0 + z1;

    float d2 = fmaf(fx, fx, fmaf(fy, fy, fz * fz));
    d2 = fmaxf(d2, 1e-24f);
    float r = rsqrtf(d2);
    r = r * fmaf(-0.5f * d2 * r, r, 1.5f);  // one Newton step for the final normalize

    out[3 * n + 0] = fx * r;
    out[3 * n + 1] = fy * r;
    out[3 * n + 2] = fz * r;
}

extern "C" void kernel_launch(void* const* d_in, const int* in_sizes, int n_in,
                              void* d_out, int out_size)
{
    const float* pos = (const float*)d_in[0];
    const float* nbr = (const float*)d_in[1];
    const float* W1  = (const float*)d_in[2];
    const float* b1  = (const float*)d_in[3];
    const float* W2  = (const float*)d_in[4];
    const float* b2  = (const float*)d_in[5];
    const float* W3  = (const float*)d_in[6];
    const float* b3  = (const float*)d_in[7];
    float* out = (float*)d_out;

    int N = in_sizes[0] / 3;  // positions is [N,3]
    int threads = 128;
    int blocks = (N + threads - 1) / threads;
    velvec_kernel<<<blocks, threads>>>(pos, nbr, W1, b1, W2, b2, W3, b3, out, N);
}

// round 2
// speedup vs baseline: 1.0821x; 1.0821x over previous
#include <cuda_runtime.h>

typedef unsigned long long u64;

// Packed (v,v) pre-scaled weights in the constant bank.
// Layout: [0:15) W1, [15:20) b1, [20:45) 0.5*W2, [45:50) b2, [50:55) 0.5*W3, [55] b3
__constant__ u64 c_w[60];
__device__ u64 g_pack[60];

__global__ void pack_weights_kernel(const float* __restrict__ W1, const float* __restrict__ b1,
                                    const float* __restrict__ W2, const float* __restrict__ b2,
                                    const float* __restrict__ W3, const float* __restrict__ b3)
{
    int i = threadIdx.x;
    if (i >= 60) return;
    float v = 0.0f;
    if      (i < 15) v = W1[i];
    else if (i < 20) v = b1[i - 15];
    else if (i < 45) v = 0.5f * W2[i - 20];
    else if (i < 50) v = b2[i - 45];
    else if (i < 55) v = 0.5f * W3[i - 50];
    else if (i == 55) v = b3[0];
    unsigned int u = __float_as_uint(v);
    g_pack[i] = ((u64)u << 32) | (u64)u;
}

// ---------- packed f32x2 helpers (Blackwell FFMA2 path) ----------
__device__ __forceinline__ u64 pk2(float lo, float hi) {
    u64 r;
    asm("mov.b64 %0, {%1, %2};" : "=l"(r)
        : "r"(__float_as_uint(lo)), "r"(__float_as_uint(hi)));
    return r;
}
__device__ __forceinline__ void upk(u64 a, float& lo, float& hi) {
    unsigned int l_, h_;
    asm("mov.b64 {%0, %1}, %2;" : "=r"(l_), "=r"(h_) : "l"(a));
    lo = __uint_as_float(l_);
    hi = __uint_as_float(h_);
}
__device__ __forceinline__ u64 dfma(u64 a, u64 b, u64 c) {
    u64 d;
    asm("fma.rn.f32x2 %0, %1, %2, %3;" : "=l"(d) : "l"(a), "l"(b), "l"(c));
    return d;
}
__device__ __forceinline__ u64 dmul(u64 a, u64 b) {
    u64 d;
    asm("mul.rn.f32x2 %0, %1, %2;" : "=l"(d) : "l"(a), "l"(b));
    return d;
}
__device__ __forceinline__ u64 dadd(u64 a, u64 b) {
    u64 d;
    asm("add.rn.f32x2 %0, %1, %2;" : "=l"(d) : "l"(a), "l"(b));
    return d;
}
// 2*relu(x) per half, exact: x + |x|  (2x folded into pre-halved W2/W3)
__device__ __forceinline__ u64 drelu2(u64 a) {
    return dadd(a, a & 0x7FFFFFFF7FFFFFFFULL);
}

// Process a packed pair of neighbors; weights come straight from the constant bank.
__device__ __forceinline__ void pair_step(
    u64 ax, u64 ay, u64 az,
    u64 npx, u64 npy, u64 npz,
    u64& vx, u64& vy, u64& vz)
{
    u64 dx = dadd(ax, npx);
    u64 dy = dadd(ay, npy);
    u64 dz = dadd(az, npz);
    u64 d2 = dfma(dx, dx, dfma(dy, dy, dmul(dz, dz)));
    float a, b;
    upk(d2, a, b);
    float ia = rsqrtf(fmaxf(a, 1e-24f));   // matches v/max(||v||,1e-12)
    float ib = rsqrtf(fmaxf(b, 1e-24f));
    u64 inv = pk2(ia, ib);
    u64 nx = dmul(dx, inv);
    u64 ny = dmul(dy, inv);
    u64 nz = dmul(dz, inv);

    // Layer 1
    u64 h0 = dfma(nz, c_w[2],  dfma(ny, c_w[1],  dfma(nx, c_w[0],  c_w[15])));
    u64 h1 = dfma(nz, c_w[5],  dfma(ny, c_w[4],  dfma(nx, c_w[3],  c_w[16])));
    u64 h2 = dfma(nz, c_w[8],  dfma(ny, c_w[7],  dfma(nx, c_w[6],  c_w[17])));
    u64 h3 = dfma(nz, c_w[11], dfma(ny, c_w[10], dfma(nx, c_w[9],  c_w[18])));
    u64 h4 = dfma(nz, c_w[14], dfma(ny, c_w[13], dfma(nx, c_w[12], c_w[19])));
    h0 = drelu2(h0); h1 = drelu2(h1); h2 = drelu2(h2); h3 = drelu2(h3); h4 = drelu2(h4);

    // Layer 2 (weights pre-scaled by 0.5)
    u64 g0 = c_w[45], g1 = c_w[46], g2 = c_w[47], g3 = c_w[48], g4 = c_w[49];
    g0 = dfma(h0, c_w[20], g0); g0 = dfma(h1, c_w[21], g0); g0 = dfma(h2, c_w[22], g0);
    g0 = dfma(h3, c_w[23], g0); g0 = dfma(h4, c_w[24], g0);
    g1 = dfma(h0, c_w[25], g1); g1 = dfma(h1, c_w[26], g1); g1 = dfma(h2, c_w[27], g1);
    g1 = dfma(h3, c_w[28], g1); g1 = dfma(h4, c_w[29], g1);
    g2 = dfma(h0, c_w[30], g2); g2 = dfma(h1, c_w[31], g2); g2 = dfma(h2, c_w[32], g2);
    g2 = dfma(h3, c_w[33], g2); g2 = dfma(h4, c_w[34], g2);
    g3 = dfma(h0, c_w[35], g3); g3 = dfma(h1, c_w[36], g3); g3 = dfma(h2, c_w[37], g3);
    g3 = dfma(h3, c_w[38], g3); g3 = dfma(h4, c_w[39], g3);
    g4 = dfma(h0, c_w[40], g4); g4 = dfma(h1, c_w[41], g4); g4 = dfma(h2, c_w[42], g4);
    g4 = dfma(h3, c_w[43], g4); g4 = dfma(h4, c_w[44], g4);
    g0 = drelu2(g0); g1 = drelu2(g1); g2 = drelu2(g2); g3 = drelu2(g3); g4 = drelu2(g4);

    // Layer 3 (pre-scaled by 0.5)
    u64 w = c_w[55];
    w = dfma(g0, c_w[50], w); w = dfma(g1, c_w[51], w); w = dfma(g2, c_w[52], w);
    w = dfma(g3, c_w[53], w); w = dfma(g4, c_w[54], w);

    // vel += nd * w
    vx = dfma(nx, w, vx);
    vy = dfma(ny, w, vy);
    vz = dfma(nz, w, vz);
}

__global__ void __launch_bounds__(128)
velvec_kernel(const float* __restrict__ pos, const float* __restrict__ nbr,
              float* __restrict__ out, int N)
{
    int n = blockIdx.x * blockDim.x + threadIdx.x;
    if (n >= N) return;

    float px = pos[3 * n + 0];
    float py = pos[3 * n + 1];
    float pz = pos[3 * n + 2];
    u64 npx = pk2(-px, -px), npy = pk2(-py, -py), npz = pk2(-pz, -pz);

    u64 vx = 0ULL, vy = 0ULL, vz = 0ULL;  // (+0.f, +0.f)

    // 32 neighbors * 3 floats = 96 floats = 24 float4 per point (384B aligned).
    const float4* base = reinterpret_cast<const float4*>(nbr) + (size_t)n * 24;

#pragma unroll 2
    for (int g = 0; g < 8; g++) {
        float4 q0 = base[3 * g + 0];  // x0 y0 z0 x1
        float4 q1 = base[3 * g + 1];  // y1 z1 x2 y2
        float4 q2 = base[3 * g + 2];  // z2 x3 y3 z3
        pair_step(pk2(q0.x, q0.w), pk2(q0.y, q1.x), pk2(q0.z, q1.y),
                  npx, npy, npz, vx, vy, vz);
        pair_step(pk2(q1.z, q2.y), pk2(q1.w, q2.z), pk2(q2.x, q2.w),
                  npx, npy, npz, vx, vy, vz);
    }

    float x0, x1, y0, y1, z0, z1;
    upk(vx, x0, x1); upk(vy, y0, y1); upk(vz, z0, z1);
    float fx = x0 + x1, fy = y0 + y1, fz = z0 + z1;

    float d2 = fmaf(fx, fx, fmaf(fy, fy, fz * fz));
    d2 = fmaxf(d2, 1e-24f);
    float r = rsqrtf(d2);
    r = r * fmaf(-0.5f * d2 * r, r, 1.5f);  // one Newton step for the final normalize

    out[3 * n + 0] = fx * r;
    out[3 * n + 1] = fy * r;
    out[3 * n + 2] = fz * r;
}

extern "C" void kernel_launch(void* const* d_in, const int* in_sizes, int n_in,
                              void* d_out, int out_size)
{
    const float* pos = (const float*)d_in[0];
    const float* nbr = (const float*)d_in[1];
    const float* W1  = (const float*)d_in[2];
    const float* b1  = (const float*)d_in[3];
    const float* W2  = (const float*)d_in[4];
    const float* b2  = (const float*)d_in[5];
    const float* W3  = (const float*)d_in[6];
    const float* b3  = (const float*)d_in[7];
    float* out = (float*)d_out;

    // 1) pack + pre-scale weights into a __device__ buffer
    pack_weights_kernel<<<1, 64>>>(W1, b1, W2, b2, W3, b3);

    // 2) D2D async copy into the constant bank (graph-capturable memcpy node)
    void* src = nullptr;
    cudaGetSymbolAddress(&src, g_pack);
    cudaMemcpyToSymbolAsync(c_w, src, 60 * sizeof(u64), 0,
                            cudaMemcpyDeviceToDevice, 0);

    // 3) main kernel
    int N = in_sizes[0] / 3;  // positions is [N,3]
    int threads = 128;
    int blocks = (N + threads - 1) / threads;
    velvec_kernel<<<blocks, threads>>>(pos, nbr, out, N);
}